// round 10
// baseline (speedup 1.0000x reference)
#include <cuda_runtime.h>
#include <math.h>

#define B_    256
#define NH    6
#define NT    343
#define HD    32
#define CDIM  192
#define MROWS (B_*NT)          // 87808 = 686*128
#define QSCALE 0.17677669529663687f   // 32^-0.5

// ---------------- scratch (device globals; no allocation allowed) -----------
__device__ float g_q[(size_t)B_*NH*NT*HD];
__device__ float g_k[(size_t)B_*NH*NT*HD];
__device__ float g_v[(size_t)B_*NH*NT*HD];
__device__ float g_ao[(size_t)MROWS*CDIM];
__device__ float g_bias[(size_t)NH*NT*NT];

// ---------------- bias materialization: biasmat[h][q][k] --------------------
__global__ void bias_kernel(const float* __restrict__ table,
                            const int*   __restrict__ ridx) {
    int i = blockIdx.x * blockDim.x + threadIdx.x;   // over NT*NT
    if (i >= NT*NT) return;
    int idx = ridx[i];
    #pragma unroll
    for (int h = 0; h < NH; h++)
        g_bias[(size_t)h*NT*NT + i] = table[idx*NH + h];
}

// ---------------- SGEMM: C[M,Nc] = A[M,K=192] @ W[Nc,K]^T + bias ------------
// Double-buffered smem stages; MODE 0 scatters qkv, MODE 1 writes d_out.
#define BM 128
#define BN 64
#define BK 16
#define ASTR 132
#define BSTR 68

template<int MODE>
__global__ void __launch_bounds__(256)
gemm_kernel(const float* __restrict__ A_in,
            const float* __restrict__ W,
            const float* __restrict__ bias,
            float*       __restrict__ out) {
    __shared__ __align__(16) float As[2][BK * ASTR];
    __shared__ __align__(16) float Bs[2][BK * BSTR];
    const float* __restrict__ A = (MODE == 0) ? A_in : g_ao;
    const int t  = threadIdx.x;
    const int m0 = blockIdx.y * BM;
    const int n0 = blockIdx.x * BN;
    const int tx = t & 15;
    const int ty = t >> 4;
    const int lrow = t >> 2;        // 0..63
    const int lk4  = (t & 3) * 4;   // 0,4,8,12

    const float* pa0 = &A[(size_t)(m0 + lrow)      * CDIM + lk4];
    const float* pa1 = &A[(size_t)(m0 + lrow + 64) * CDIM + lk4];
    const float* pw  = &W[(size_t)(n0 + lrow)      * CDIM + lk4];

    float acc[8][4] = {};

    {
        float4 a0 = *(const float4*)pa0;
        float4 a1 = *(const float4*)pa1;
        float4 wv = *(const float4*)pw;
        As[0][(lk4+0)*ASTR + lrow] = a0.x; As[0][(lk4+1)*ASTR + lrow] = a0.y;
        As[0][(lk4+2)*ASTR + lrow] = a0.z; As[0][(lk4+3)*ASTR + lrow] = a0.w;
        As[0][(lk4+0)*ASTR + lrow + 64] = a1.x; As[0][(lk4+1)*ASTR + lrow + 64] = a1.y;
        As[0][(lk4+2)*ASTR + lrow + 64] = a1.z; As[0][(lk4+3)*ASTR + lrow + 64] = a1.w;
        Bs[0][(lk4+0)*BSTR + lrow] = wv.x; Bs[0][(lk4+1)*BSTR + lrow] = wv.y;
        Bs[0][(lk4+2)*BSTR + lrow] = wv.z; Bs[0][(lk4+3)*BSTR + lrow] = wv.w;
    }
    __syncthreads();

    int stage = 0;
    for (int k0 = 0; k0 < CDIM; k0 += BK) {
        float4 na0, na1, nwv;
        const bool has_next = (k0 + BK < CDIM);
        if (has_next) {
            na0 = *(const float4*)(pa0 + k0 + BK);
            na1 = *(const float4*)(pa1 + k0 + BK);
            nwv = *(const float4*)(pw  + k0 + BK);
        }
        const float* as = As[stage];
        const float* bs = Bs[stage];
        #pragma unroll
        for (int kk = 0; kk < BK; kk++) {
            float4 av0 = *(const float4*)&as[kk*ASTR + ty*8];
            float4 av1 = *(const float4*)&as[kk*ASTR + ty*8 + 4];
            float4 bv  = *(const float4*)&bs[kk*BSTR + tx*4];
            float a[8] = {av0.x, av0.y, av0.z, av0.w, av1.x, av1.y, av1.z, av1.w};
            float b[4] = {bv.x, bv.y, bv.z, bv.w};
            #pragma unroll
            for (int i = 0; i < 8; i++)
                #pragma unroll
                for (int j = 0; j < 4; j++)
                    acc[i][j] += a[i] * b[j];
        }
        if (has_next) {
            const int ns = stage ^ 1;
            As[ns][(lk4+0)*ASTR + lrow] = na0.x; As[ns][(lk4+1)*ASTR + lrow] = na0.y;
            As[ns][(lk4+2)*ASTR + lrow] = na0.z; As[ns][(lk4+3)*ASTR + lrow] = na0.w;
            As[ns][(lk4+0)*ASTR + lrow + 64] = na1.x; As[ns][(lk4+1)*ASTR + lrow + 64] = na1.y;
            As[ns][(lk4+2)*ASTR + lrow + 64] = na1.z; As[ns][(lk4+3)*ASTR + lrow + 64] = na1.w;
            Bs[ns][(lk4+0)*BSTR + lrow] = nwv.x; Bs[ns][(lk4+1)*BSTR + lrow] = nwv.y;
            Bs[ns][(lk4+2)*BSTR + lrow] = nwv.z; Bs[ns][(lk4+3)*BSTR + lrow] = nwv.w;
            __syncthreads();
        }
        stage ^= 1;
    }

    #pragma unroll
    for (int i = 0; i < 8; i++) {
        int m = m0 + ty * 8 + i;
        #pragma unroll
        for (int j = 0; j < 4; j++) {
            int c = n0 + tx * 4 + j;
            float v = acc[i][j] + bias[c];
            if (MODE == 0) {
                int b = m / NT, n = m - b * NT;
                int s = c / CDIM;
                int hc = c - s * CDIM;
                int h = hc >> 5, d = hc & 31;
                size_t dst = ((size_t)(b * NH + h) * NT + n) * HD + d;
                if      (s == 0) g_q[dst] = v * QSCALE;
                else if (s == 1) g_k[dst] = v;
                else             g_v[dst] = v;
            } else {
                out[(size_t)m * CDIM + c] = v;
            }
        }
    }
}

// ---------------- attention: one CTA per (b,h), 8 warps, 2 rows/warp --------
// P stays in registers; V read by key (lane=key) like K; output dims
// reassembled with a register butterfly transpose-reduce.
// NOTE: launch bounds are (256) with NO min-blocks — forcing 2 CTAs/SM caps
// regs at 128 and spills q4/p/acc to local memory (Round 7: 4.6x slowdown).
#define KSTR 36    // %32==4 -> conflict-free LDS.128 across lanes
#define AT_SMEM_FLOATS (2*NT*KSTR + 8*2*32)

template<int NR>
__device__ __forceinline__ void attn_pair(
    int r0, const float* __restrict__ ks, const float* __restrict__ vs,
    float* __restrict__ qw,   // [NR][32] staging
    const float* __restrict__ bm, size_t base, int b, int h, int lane)
{
    __syncwarp();   // protect qw reuse across iterations
    #pragma unroll
    for (int rr = 0; rr < NR; rr++)
        qw[rr*32 + lane] = g_q[base + (size_t)(r0+rr) * HD + lane];
    __syncwarp();
    float4 q4[NR][8];
    #pragma unroll
    for (int rr = 0; rr < NR; rr++)
        #pragma unroll
        for (int i = 0; i < 8; i++)
            q4[rr][i] = *(const float4*)&qw[rr*32 + i*4];

    // ---- scores (kept in registers) ----
    float p[NR][11];
    float mx[NR];
    #pragma unroll
    for (int rr = 0; rr < NR; rr++) mx[rr] = -1e30f;

    #pragma unroll
    for (int tt = 0; tt < 11; tt++) {
        int j = tt * 32 + lane;
        float s[NR];
        if (j < NT) {
            #pragma unroll
            for (int rr = 0; rr < NR; rr++)
                s[rr] = bm[(size_t)(r0+rr) * NT + j];
            const float4* kr = (const float4*)&ks[j * KSTR];
            #pragma unroll
            for (int i = 0; i < 8; i++) {
                float4 k4 = kr[i];
                #pragma unroll
                for (int rr = 0; rr < NR; rr++) {
                    s[rr] += q4[rr][i].x * k4.x;
                    s[rr] += q4[rr][i].y * k4.y;
                    s[rr] += q4[rr][i].z * k4.z;
                    s[rr] += q4[rr][i].w * k4.w;
                }
            }
        } else {
            #pragma unroll
            for (int rr = 0; rr < NR; rr++) s[rr] = -1e30f;
        }
        #pragma unroll
        for (int rr = 0; rr < NR; rr++) {
            p[rr][tt] = s[rr];
            mx[rr] = fmaxf(mx[rr], s[rr]);
        }
    }
    #pragma unroll
    for (int rr = 0; rr < NR; rr++)
        #pragma unroll
        for (int o = 16; o; o >>= 1)
            mx[rr] = fmaxf(mx[rr], __shfl_xor_sync(0xffffffffu, mx[rr], o));

    // ---- exp + row sums (registers only) ----
    float sum[NR];
    #pragma unroll
    for (int rr = 0; rr < NR; rr++) sum[rr] = 0.f;
    #pragma unroll
    for (int tt = 0; tt < 11; tt++) {
        int j = tt * 32 + lane;
        #pragma unroll
        for (int rr = 0; rr < NR; rr++) {
            float e = (j < NT) ? __expf(p[rr][tt] - mx[rr]) : 0.f;
            p[rr][tt] = e;
            sum[rr] += e;
        }
    }
    float inv[NR];
    #pragma unroll
    for (int rr = 0; rr < NR; rr++) {
        #pragma unroll
        for (int o = 16; o; o >>= 1)
            sum[rr] += __shfl_xor_sync(0xffffffffu, sum[rr], o);
        inv[rr] = __frcp_rn(sum[rr]);
    }

    // ---- P @ V by key, in two 16-dim halves ----
    #pragma unroll
    for (int dh = 0; dh < 2; dh++) {
        float acc[NR][16];
        #pragma unroll
        for (int rr = 0; rr < NR; rr++)
            #pragma unroll
            for (int d = 0; d < 16; d++) acc[rr][d] = 0.f;

        #pragma unroll
        for (int tt = 0; tt < 11; tt++) {
            int j = tt * 32 + lane;
            if (j < NT) {
                const float4* vr = (const float4*)&vs[j * KSTR + dh * 16];
                #pragma unroll
                for (int qd = 0; qd < 4; qd++) {
                    float4 v4 = vr[qd];
                    #pragma unroll
                    for (int rr = 0; rr < NR; rr++) {
                        acc[rr][qd*4+0] += p[rr][tt] * v4.x;
                        acc[rr][qd*4+1] += p[rr][tt] * v4.y;
                        acc[rr][qd*4+2] += p[rr][tt] * v4.z;
                        acc[rr][qd*4+3] += p[rr][tt] * v4.w;
                    }
                }
            }
        }

        // butterfly transpose-reduce: after stages, acc[rr][0] on lane l
        // holds dim (l & 15) summed over all 32 lanes.
        #pragma unroll
        for (int rr = 0; rr < NR; rr++) {
            #pragma unroll
            for (int o = 8; o >= 1; o >>= 1) {
                #pragma unroll
                for (int d = 0; d < o; d++) {
                    float lo = acc[rr][d], hi = acc[rr][d+o];
                    float send = (lane & o) ? lo : hi;
                    float recv = __shfl_xor_sync(0xffffffffu, send, o);
                    acc[rr][d] = ((lane & o) ? hi : lo) + recv;
                }
            }
            acc[rr][0] += __shfl_xor_sync(0xffffffffu, acc[rr][0], 16);
        }

        int d = lane & 15;
        if (NR == 2) {
            int rsel = lane >> 4;   // lanes 0-15 -> row r0, 16-31 -> row r0+1
            float oval = (lane < 16) ? acc[0][0] * inv[0]
                                     : acc[NR-1][0] * inv[NR-1];
            g_ao[((size_t)b * NT + r0 + rsel) * CDIM + h * HD + dh*16 + d] = oval;
        } else {
            if (lane < 16)
                g_ao[((size_t)b * NT + r0) * CDIM + h * HD + dh*16 + d] =
                    acc[0][0] * inv[0];
        }
    }
}

__global__ void __launch_bounds__(256) attn_kernel() {
    extern __shared__ float sm[];
    float* ks = sm;                    // [NT][KSTR]
    float* vs = ks + NT * KSTR;        // [NT][KSTR]
    float* qs = vs + NT * KSTR;        // [8][2][32]

    const int bh = blockIdx.x;               // 0..1535
    const int b  = bh / NH, h = bh % NH;
    const size_t base = (size_t)bh * NT * HD;
    const int t = threadIdx.x;

    for (int i = t; i < NT * HD / 4; i += 256) {
        int e = i * 4;
        int j = e >> 5, d = e & 31;
        *(float4*)&ks[j * KSTR + d] = *(const float4*)&g_k[base + e];
        *(float4*)&vs[j * KSTR + d] = *(const float4*)&g_v[base + e];
    }
    __syncthreads();

    const int w = t >> 5, lane = t & 31;
    const float* __restrict__ bm = &g_bias[(size_t)h * NT * NT];
    float* qw = &qs[w * 2 * 32];

    for (int r = 2 * w; r < NT - 1; r += 16)
        attn_pair<2>(r, ks, vs, qw, bm, base, b, h, lane);
    if (w == 3)   // row 342: 342 = 2*171, 171 mod 8 == 3
        attn_pair<1>(NT - 1, ks, vs, qw, bm, base, b, h, lane);
}

// ---------------- launch ----------------------------------------------------
extern "C" void kernel_launch(void* const* d_in, const int* in_sizes, int n_in,
                              void* d_out, int out_size) {
    const float* x      = (const float*)d_in[0];
    const float* w_qkv  = (const float*)d_in[1];
    const float* b_qkv  = (const float*)d_in[2];
    const float* w_proj = (const float*)d_in[3];
    const float* b_proj = (const float*)d_in[4];
    const float* table  = (const float*)d_in[5];
    const int*   ridx   = (const int*)d_in[6];
    float* out = (float*)d_out;

    // 1) bias gather
    bias_kernel<<<(NT*NT + 255) / 256, 256>>>(table, ridx);

    // 2) QKV GEMM (scatter epilogue)
    gemm_kernel<0><<<dim3(576 / BN, MROWS / BM), 256>>>(x, w_qkv, b_qkv, nullptr);

    // 3) attention
    const int smem_bytes = AT_SMEM_FLOATS * (int)sizeof(float);  // ~98.5 KB
    cudaFuncSetAttribute(attn_kernel,
                         cudaFuncAttributeMaxDynamicSharedMemorySize, smem_bytes);
    attn_kernel<<<B_ * NH, 256, smem_bytes>>>();

    // 4) output projection
    gemm_kernel<1><<<dim3(CDIM / BN, MROWS / BM), 256>>>(nullptr, w_proj, b_proj, out);
}

// round 11
// speedup vs baseline: 8.7411x; 8.7411x over previous
#include <cuda_runtime.h>
#include <mma.h>
#include <math.h>

using namespace nvcuda;

#define B_    256
#define NH    6
#define NT    343
#define HD    32
#define CDIM  192
#define MROWS (B_*NT)          // 87808 = 686*128
#define QSCALE 0.17677669529663687f   // 32^-0.5

// ---------------- scratch (device globals; no allocation allowed) -----------
__device__ float g_q[(size_t)B_*NH*NT*HD];
__device__ float g_k[(size_t)B_*NH*NT*HD];
__device__ float g_v[(size_t)B_*NH*NT*HD];
__device__ float g_ao[(size_t)MROWS*CDIM];
__device__ float g_bias[(size_t)NH*NT*NT];

// ---------------- bias materialization: biasmat[h][q][k] --------------------
__global__ void bias_kernel(const float* __restrict__ table,
                            const int*   __restrict__ ridx) {
    int i = blockIdx.x * blockDim.x + threadIdx.x;   // over NT*NT
    if (i >= NT*NT) return;
    int idx = ridx[i];
    #pragma unroll
    for (int h = 0; h < NH; h++)
        g_bias[(size_t)h*NT*NT + i] = table[idx*NH + h];
}

// ---------------- tf32 tensor-core GEMM ------------------------------------
// C[M,Nc] = A[M,192] @ W[Nc,192]^T + bias
// MODE 0: A = x, Nc=576, epilogue scatters to g_q/g_k/g_v (scale on q)
// MODE 1: A = g_ao, Nc=192, epilogue writes d_out
// W row-major [n][k] is exactly wmma matrix_b col_major with ld = stride.
#define BM 128
#define BN 64
#define BKC 32
#define AST 40     // padded strides (multiple of 8)
#define BST 40
#define CST 20     // accumulator stage stride (multiple of 4)

template<int MODE>
__global__ void __launch_bounds__(256)
gemm_tc(const float* __restrict__ A_in,
        const float* __restrict__ W,
        const float* __restrict__ bias,
        float*       __restrict__ out) {
    __shared__ __align__(16) float As[BM * AST];      // 20 KB
    __shared__ __align__(16) float Bs[BN * BST];      // 10 KB
    __shared__ __align__(16) float Cs[8 * 16 * CST];  // 10 KB (per-warp stage)

    const float* __restrict__ A = (MODE == 0) ? A_in : g_ao;
    const int t    = threadIdx.x;
    const int warp = t >> 5;
    const int lane = t & 31;
    const int m0 = blockIdx.y * BM;
    const int n0 = blockIdx.x * BN;
    const int wm = warp & 3;     // 4 warps along M (32 rows each)
    const int wn = warp >> 2;    // 2 warps along N (32 cols each)

    wmma::fragment<wmma::accumulator, 16, 16, 8, float> c[2][2];
    #pragma unroll
    for (int i = 0; i < 2; i++)
        #pragma unroll
        for (int j = 0; j < 2; j++)
            wmma::fill_fragment(c[i][j], 0.0f);

    for (int k0 = 0; k0 < CDIM; k0 += BKC) {
        // stage A chunk: 128 rows x 32 k (2 threads/row, 16 floats each)
        {
            int row = t >> 1, ko = (t & 1) * 16;
            const float* src = &A[(size_t)(m0 + row) * CDIM + k0 + ko];
            float* dst = &As[row * AST + ko];
            #pragma unroll
            for (int u = 0; u < 4; u++)
                *(float4*)(dst + u * 4) = *(const float4*)(src + u * 4);
        }
        // stage W chunk: 64 rows x 32 k (4 threads/row, 8 floats each)
        {
            int row = t >> 2, ko = (t & 3) * 8;
            const float* src = &W[(size_t)(n0 + row) * CDIM + k0 + ko];
            float* dst = &Bs[row * BST + ko];
            *(float4*)(dst)     = *(const float4*)(src);
            *(float4*)(dst + 4) = *(const float4*)(src + 4);
        }
        __syncthreads();

        #pragma unroll
        for (int kk = 0; kk < BKC; kk += 8) {
            wmma::fragment<wmma::matrix_a, 16, 16, 8, wmma::precision::tf32,
                           wmma::row_major> a[2];
            wmma::fragment<wmma::matrix_b, 16, 16, 8, wmma::precision::tf32,
                           wmma::col_major> b[2];
            #pragma unroll
            for (int i = 0; i < 2; i++) {
                wmma::load_matrix_sync(a[i], &As[(wm * 32 + i * 16) * AST + kk], AST);
                #pragma unroll
                for (int e = 0; e < a[i].num_elements; e++)
                    a[i].x[e] = wmma::__float_to_tf32(a[i].x[e]);
            }
            #pragma unroll
            for (int j = 0; j < 2; j++) {
                wmma::load_matrix_sync(b[j], &Bs[(wn * 32 + j * 16) * BST + kk], BST);
                #pragma unroll
                for (int e = 0; e < b[j].num_elements; e++)
                    b[j].x[e] = wmma::__float_to_tf32(b[j].x[e]);
            }
            #pragma unroll
            for (int i = 0; i < 2; i++)
                #pragma unroll
                for (int j = 0; j < 2; j++)
                    wmma::mma_sync(c[i][j], a[i], b[j], c[i][j]);
        }
        __syncthreads();
    }

    // epilogue: stage each frag through per-warp smem patch, bias + store/scatter
    float* cw = &Cs[warp * 16 * CST];
    #pragma unroll
    for (int i = 0; i < 2; i++) {
        #pragma unroll
        for (int j = 0; j < 2; j++) {
            wmma::store_matrix_sync(cw, c[i][j], CST, wmma::mem_row_major);
            __syncwarp();
            #pragma unroll
            for (int e = 0; e < 8; e++) {
                int idx = lane * 8 + e;          // 0..255
                int row = idx >> 4, col = idx & 15;
                int m = m0 + wm * 32 + i * 16 + row;
                int cc = n0 + wn * 32 + j * 16 + col;
                float v = cw[row * CST + col] + bias[cc];
                if (MODE == 0) {
                    int bb = m / NT, n = m - bb * NT;
                    int s = cc / CDIM;
                    int hc = cc - s * CDIM;
                    int h = hc >> 5, d = hc & 31;
                    size_t dst = ((size_t)(bb * NH + h) * NT + n) * HD + d;
                    if      (s == 0) g_q[dst] = v * QSCALE;
                    else if (s == 1) g_k[dst] = v;
                    else             g_v[dst] = v;
                } else {
                    out[(size_t)m * CDIM + cc] = v;
                }
            }
            __syncwarp();
        }
    }
}

// ---------------- attention (Round-5 proven version, verbatim) --------------
// smem: ks[NT][36] | vt[HD][348] (V transposed) | ps[8][2][344] | qs[8][2][32]
#define KSTR 36    // %32==4 -> conflict-free LDS.128 across lanes
#define VSTR 348   // conflict-free LDS.128 (4L mod-32 tiling)
#define PSTR 344   // 343 rounded to multiple of 4, zero-padded tail
#define AT_SMEM_FLOATS (NT*KSTR + HD*VSTR + 8*2*PSTR + 8*2*32)

template<int NR>
__device__ __forceinline__ void attn_rows(
    int r0, const float* __restrict__ ks, const float* __restrict__ vt,
    float* __restrict__ pw,   // [NR][PSTR]
    float* __restrict__ qw,   // [NR][32]
    const float* __restrict__ bm, size_t base, int b, int h, int lane)
{
    #pragma unroll
    for (int rr = 0; rr < NR; rr++)
        qw[rr*32 + lane] = g_q[base + (size_t)(r0+rr) * HD + lane];
    __syncwarp();
    float4 q4[NR][8];
    #pragma unroll
    for (int rr = 0; rr < NR; rr++)
        #pragma unroll
        for (int i = 0; i < 8; i++)
            q4[rr][i] = *(const float4*)&qw[rr*32 + i*4];

    float sc[NR][11];
    float mx[NR];
    #pragma unroll
    for (int rr = 0; rr < NR; rr++) mx[rr] = -1e30f;

    #pragma unroll
    for (int tt = 0; tt < 11; tt++) {
        int j = tt * 32 + lane;
        float s[NR];
        if (j < NT) {
            #pragma unroll
            for (int rr = 0; rr < NR; rr++)
                s[rr] = bm[(size_t)(r0+rr) * NT + j];
            const float4* kr = (const float4*)&ks[j * KSTR];
            #pragma unroll
            for (int i = 0; i < 8; i++) {
                float4 k4 = kr[i];
                #pragma unroll
                for (int rr = 0; rr < NR; rr++) {
                    s[rr] += q4[rr][i].x * k4.x;
                    s[rr] += q4[rr][i].y * k4.y;
                    s[rr] += q4[rr][i].z * k4.z;
                    s[rr] += q4[rr][i].w * k4.w;
                }
            }
        } else {
            #pragma unroll
            for (int rr = 0; rr < NR; rr++) s[rr] = -1e30f;
        }
        #pragma unroll
        for (int rr = 0; rr < NR; rr++) {
            sc[rr][tt] = s[rr];
            mx[rr] = fmaxf(mx[rr], s[rr]);
        }
    }
    #pragma unroll
    for (int rr = 0; rr < NR; rr++)
        #pragma unroll
        for (int o = 16; o; o >>= 1)
            mx[rr] = fmaxf(mx[rr], __shfl_xor_sync(0xffffffffu, mx[rr], o));

    float sum[NR];
    #pragma unroll
    for (int rr = 0; rr < NR; rr++) sum[rr] = 0.f;
    #pragma unroll
    for (int tt = 0; tt < 11; tt++) {
        int j = tt * 32 + lane;
        #pragma unroll
        for (int rr = 0; rr < NR; rr++) {
            if (j < NT) {
                float e = __expf(sc[rr][tt] - mx[rr]);
                pw[rr*PSTR + j] = e;
                sum[rr] += e;
            } else if (j < PSTR) {
                pw[rr*PSTR + j] = 0.f;
            }
        }
    }
    float inv[NR];
    #pragma unroll
    for (int rr = 0; rr < NR; rr++) {
        #pragma unroll
        for (int o = 16; o; o >>= 1)
            sum[rr] += __shfl_xor_sync(0xffffffffu, sum[rr], o);
        inv[rr] = __frcp_rn(sum[rr]);
    }
    __syncwarp();

    // P @ V : lane == output dim d; V row loaded once per NR rows
    float acc[NR];
    #pragma unroll
    for (int rr = 0; rr < NR; rr++) acc[rr] = 0.f;
    const float4* vrow = (const float4*)&vt[lane * VSTR];
    #pragma unroll 2
    for (int jj = 0; jj < PSTR / 4; jj++) {
        float4 v4 = vrow[jj];
        #pragma unroll
        for (int rr = 0; rr < NR; rr++) {
            float4 p4 = *(const float4*)&pw[rr*PSTR + jj*4];
            acc[rr] += p4.x * v4.x;
            acc[rr] += p4.y * v4.y;
            acc[rr] += p4.z * v4.z;
            acc[rr] += p4.w * v4.w;
        }
    }
    #pragma unroll
    for (int rr = 0; rr < NR; rr++)
        g_ao[((size_t)b * NT + (r0+rr)) * CDIM + h * HD + lane] = acc[rr] * inv[rr];
    __syncwarp();
}

__global__ void __launch_bounds__(256) attn_kernel() {
    extern __shared__ float sm[];
    float* ks = sm;                    // [NT][KSTR]
    float* vt = ks + NT * KSTR;        // [HD][VSTR] transposed V
    float* ps = vt + HD * VSTR;        // [8][2][PSTR]
    float* qs = ps + 8 * 2 * PSTR;     // [8][2][32]

    const int bh = blockIdx.x;               // 0..1535
    const int b  = bh / NH, h = bh % NH;
    const size_t base = (size_t)bh * NT * HD;
    const int t = threadIdx.x;

    for (int i = t; i < NT * HD / 4; i += 256) {
        int e = i * 4;
        int j = e >> 5, d = e & 31;
        float4 kv = *(const float4*)&g_k[base + e];
        *(float4*)&ks[j * KSTR + d] = kv;
        float4 vv = *(const float4*)&g_v[base + e];
        vt[(d+0) * VSTR + j] = vv.x;
        vt[(d+1) * VSTR + j] = vv.y;
        vt[(d+2) * VSTR + j] = vv.z;
        vt[(d+3) * VSTR + j] = vv.w;
    }
    if (t < HD) vt[t * VSTR + NT] = 0.f;   // zero padded V column
    __syncthreads();

    const int w = t >> 5, lane = t & 31;
    const float* __restrict__ bm = &g_bias[(size_t)h * NT * NT];
    float* pw = &ps[w * 2 * PSTR];
    float* qw = &qs[w * 2 * 32];

    for (int r = 2 * w; r < NT - 1; r += 16)
        attn_rows<2>(r, ks, vt, pw, qw, bm, base, b, h, lane);
    if (w == 3)   // row 342: residue class of warp 3
        attn_rows<1>(NT - 1, ks, vt, pw, qw, bm, base, b, h, lane);
}

// ---------------- launch ----------------------------------------------------
extern "C" void kernel_launch(void* const* d_in, const int* in_sizes, int n_in,
                              void* d_out, int out_size) {
    const float* x      = (const float*)d_in[0];
    const float* w_qkv  = (const float*)d_in[1];
    const float* b_qkv  = (const float*)d_in[2];
    const float* w_proj = (const float*)d_in[3];
    const float* b_proj = (const float*)d_in[4];
    const float* table  = (const float*)d_in[5];
    const int*   ridx   = (const int*)d_in[6];
    float* out = (float*)d_out;

    // 1) bias gather
    bias_kernel<<<(NT*NT + 255) / 256, 256>>>(table, ridx);

    // 2) QKV GEMM (tf32 tensor cores, scatter epilogue)
    gemm_tc<0><<<dim3(576 / BN, MROWS / BM), 256>>>(x, w_qkv, b_qkv, nullptr);

    // 3) attention (Round-5 proven)
    const int smem_bytes = AT_SMEM_FLOATS * (int)sizeof(float);  // ~118 KB
    cudaFuncSetAttribute(attn_kernel,
                         cudaFuncAttributeMaxDynamicSharedMemorySize, smem_bytes);
    attn_kernel<<<B_ * NH, 256, smem_bytes>>>();

    // 4) output projection (tf32 tensor cores)
    gemm_tc<1><<<dim3(CDIM / BN, MROWS / BM), 256>>>(nullptr, w_proj, b_proj, out);
}

// round 14
// speedup vs baseline: 10.2940x; 1.1776x over previous
#include <cuda_runtime.h>
#include <mma.h>
#include <math.h>

using namespace nvcuda;

#define B_    256
#define NH    6
#define NT    343
#define NTP   352               // 343 padded to 22*16
#define HD    32
#define CDIM  192
#define MROWS (B_*NT)           // 87808 = 686*128
#define QSCALE 0.17677669529663687f

// ---------------- scratch (device globals; no allocation allowed) -----------
__device__ float g_q[(size_t)B_*NH*NT*HD];
__device__ float g_k[(size_t)B_*NH*NT*HD];
__device__ float g_v[(size_t)B_*NH*NT*HD];
__device__ float g_ao[(size_t)MROWS*CDIM];
__device__ float g_bias[(size_t)NH*NT*NT];

// ---------------- bias materialization --------------------------------------
__global__ void bias_kernel(const float* __restrict__ table,
                            const int*   __restrict__ ridx) {
    int i = blockIdx.x * blockDim.x + threadIdx.x;
    if (i >= NT*NT) return;
    int idx = ridx[i];
    #pragma unroll
    for (int h = 0; h < NH; h++)
        g_bias[(size_t)h*NT*NT + i] = table[idx*NH + h];
}

// ---------------- FFMA SGEMM (Round-5 proven) -------------------------------
#define BM 128
#define BN 64
#define BK 16
#define ASTR 132
#define BSTR 68

template<int MODE>
__global__ void __launch_bounds__(256)
gemm_kernel(const float* __restrict__ A_in,
            const float* __restrict__ W,
            const float* __restrict__ bias,
            float*       __restrict__ out) {
    __shared__ __align__(16) float As[2][BK * ASTR];
    __shared__ __align__(16) float Bs[2][BK * BSTR];
    const float* __restrict__ A = (MODE == 0) ? A_in : g_ao;
    const int t  = threadIdx.x;
    const int m0 = blockIdx.y * BM;
    const int n0 = blockIdx.x * BN;
    const int tx = t & 15;
    const int ty = t >> 4;
    const int lrow = t >> 2;
    const int lk4  = (t & 3) * 4;

    const float* pa0 = &A[(size_t)(m0 + lrow)      * CDIM + lk4];
    const float* pa1 = &A[(size_t)(m0 + lrow + 64) * CDIM + lk4];
    const float* pw  = &W[(size_t)(n0 + lrow)      * CDIM + lk4];

    float acc[8][4] = {};

    {
        float4 a0 = *(const float4*)pa0;
        float4 a1 = *(const float4*)pa1;
        float4 wv = *(const float4*)pw;
        As[0][(lk4+0)*ASTR + lrow] = a0.x; As[0][(lk4+1)*ASTR + lrow] = a0.y;
        As[0][(lk4+2)*ASTR + lrow] = a0.z; As[0][(lk4+3)*ASTR + lrow] = a0.w;
        As[0][(lk4+0)*ASTR + lrow + 64] = a1.x; As[0][(lk4+1)*ASTR + lrow + 64] = a1.y;
        As[0][(lk4+2)*ASTR + lrow + 64] = a1.z; As[0][(lk4+3)*ASTR + lrow + 64] = a1.w;
        Bs[0][(lk4+0)*BSTR + lrow] = wv.x; Bs[0][(lk4+1)*BSTR + lrow] = wv.y;
        Bs[0][(lk4+2)*BSTR + lrow] = wv.z; Bs[0][(lk4+3)*BSTR + lrow] = wv.w;
    }
    __syncthreads();

    int stage = 0;
    for (int k0 = 0; k0 < CDIM; k0 += BK) {
        float4 na0, na1, nwv;
        const bool has_next = (k0 + BK < CDIM);
        if (has_next) {
            na0 = *(const float4*)(pa0 + k0 + BK);
            na1 = *(const float4*)(pa1 + k0 + BK);
            nwv = *(const float4*)(pw  + k0 + BK);
        }
        const float* as = As[stage];
        const float* bs = Bs[stage];
        #pragma unroll
        for (int kk = 0; kk < BK; kk++) {
            float4 av0 = *(const float4*)&as[kk*ASTR + ty*8];
            float4 av1 = *(const float4*)&as[kk*ASTR + ty*8 + 4];
            float4 bv  = *(const float4*)&bs[kk*BSTR + tx*4];
            float a[8] = {av0.x, av0.y, av0.z, av0.w, av1.x, av1.y, av1.z, av1.w};
            float b[4] = {bv.x, bv.y, bv.z, bv.w};
            #pragma unroll
            for (int i = 0; i < 8; i++)
                #pragma unroll
                for (int j = 0; j < 4; j++)
                    acc[i][j] += a[i] * b[j];
        }
        if (has_next) {
            const int ns = stage ^ 1;
            As[ns][(lk4+0)*ASTR + lrow] = na0.x; As[ns][(lk4+1)*ASTR + lrow] = na0.y;
            As[ns][(lk4+2)*ASTR + lrow] = na0.z; As[ns][(lk4+3)*ASTR + lrow] = na0.w;
            As[ns][(lk4+0)*ASTR + lrow + 64] = na1.x; As[ns][(lk4+1)*ASTR + lrow + 64] = na1.y;
            As[ns][(lk4+2)*ASTR + lrow + 64] = na1.z; As[ns][(lk4+3)*ASTR + lrow + 64] = na1.w;
            Bs[ns][(lk4+0)*BSTR + lrow] = nwv.x; Bs[ns][(lk4+1)*BSTR + lrow] = nwv.y;
            Bs[ns][(lk4+2)*BSTR + lrow] = nwv.z; Bs[ns][(lk4+3)*BSTR + lrow] = nwv.w;
            __syncthreads();
        }
        stage ^= 1;
    }

    #pragma unroll
    for (int i = 0; i < 8; i++) {
        int m = m0 + ty * 8 + i;
        #pragma unroll
        for (int j = 0; j < 4; j++) {
            int c = n0 + tx * 4 + j;
            float v = acc[i][j] + bias[c];
            if (MODE == 0) {
                int b = m / NT, n = m - b * NT;
                int s = c / CDIM;
                int hc = c - s * CDIM;
                int h = hc >> 5, d = hc & 31;
                size_t dst = ((size_t)(b * NH + h) * NT + n) * HD + d;
                if      (s == 0) g_q[dst] = v * QSCALE;
                else if (s == 1) g_k[dst] = v;
                else             g_v[dst] = v;
            } else {
                out[(size_t)m * CDIM + c] = v;
            }
        }
    }
}

// ---------------- attention: tf32 WMMA, one CTA per (b,h) -------------------
// smem: ks[NTP][36] | vs[NTP][36] | ss[64][356] | qs[64][36] | os[8][16*20]
#define KS2 36
#define SST 356
#define QB  64
#define AT_SMEM_FLOATS (2*NTP*KS2 + QB*SST + QB*KS2 + 8*16*20)

#define CVT_FRAG(f) do { _Pragma("unroll") \
    for (int _e = 0; _e < (f).num_elements; _e++) \
        (f).x[_e] = wmma::__float_to_tf32((f).x[_e]); } while (0)

__global__ void __launch_bounds__(256) attn_tc_kernel() {
    extern __shared__ float sm[];
    float* ks = sm;                       // [NTP][KS2]
    float* vs = ks + NTP * KS2;           // [NTP][KS2]
    float* ss = vs + NTP * KS2;           // [QB][SST]
    float* qs = ss + QB * SST;            // [QB][KS2]
    float* os = qs + QB * KS2;            // [8][320]

    const int bh = blockIdx.x;            // 0..1535
    const int b  = bh / NH, h = bh % NH;
    const size_t base = (size_t)bh * NT * HD;
    const int t = threadIdx.x, warp = t >> 5, lane = t & 31;

    // zero the padded K/V rows [NT, NTP)
    for (int i = t; i < (NTP - NT) * KS2; i += 256) {
        int r = NT + i / KS2, c = i % KS2;
        ks[r * KS2 + c] = 0.f;
        vs[r * KS2 + c] = 0.f;
    }
    // stage K, V
    for (int i = t; i < NT * HD / 4; i += 256) {
        int e = i * 4;
        int j = e >> 5, d = e & 31;
        *(float4*)&ks[j * KS2 + d] = *(const float4*)&g_k[base + e];
        *(float4*)&vs[j * KS2 + d] = *(const float4*)&g_v[base + e];
    }
    __syncthreads();

    const float* __restrict__ bm = &g_bias[(size_t)h * NT * NT];

    for (int qb = 0; qb < NT; qb += QB) {
        // stage Q block (zero-pad rows beyond NT)
        for (int i = t; i < QB * HD / 4; i += 256) {
            int e = i * 4;
            int r = e >> 5, d = e & 31;
            int gr = qb + r;
            float4 v = (gr < NT) ? *(const float4*)&g_q[base + (size_t)gr * HD + d]
                                 : make_float4(0.f, 0.f, 0.f, 0.f);
            *(float4*)&qs[r * KS2 + d] = v;
        }
        __syncthreads();

        // ---- S = Q @ K^T : warp -> row-tile (warp&3), 11 col-tiles ----
        {
            int rt = warp & 3;
            int c0 = (warp >> 2) * 11;
            wmma::fragment<wmma::matrix_a, 16, 16, 8, wmma::precision::tf32,
                           wmma::row_major> a[4];
            #pragma unroll
            for (int kk = 0; kk < 4; kk++) {
                wmma::load_matrix_sync(a[kk], &qs[rt * 16 * KS2 + kk * 8], KS2);
                CVT_FRAG(a[kk]);
            }
            for (int ct = c0; ct < c0 + 11; ct++) {
                wmma::fragment<wmma::accumulator, 16, 16, 8, float> acc;
                wmma::fill_fragment(acc, 0.0f);
                #pragma unroll
                for (int kk = 0; kk < 4; kk++) {
                    wmma::fragment<wmma::matrix_b, 16, 16, 8, wmma::precision::tf32,
                                   wmma::col_major> bf;
                    wmma::load_matrix_sync(bf, &ks[ct * 16 * KS2 + kk * 8], KS2);
                    CVT_FRAG(bf);
                    wmma::mma_sync(acc, a[kk], bf, acc);
                }
                wmma::store_matrix_sync(&ss[rt * 16 * SST + ct * 16], acc, SST,
                                        wmma::mem_row_major);
            }
        }
        __syncthreads();

        // ---- softmax rows (bias added here, P normalized in place) ----
        for (int rl = warp * 8; rl < warp * 8 + 8; rl++) {
            int r = qb + rl;
            if (r >= NT) break;
            float* srow = &ss[rl * SST];
            const float* brow = &bm[(size_t)r * NT];
            float v[11];
            float mx = -1e30f;
            #pragma unroll
            for (int tt = 0; tt < 11; tt++) {
                int j = tt * 32 + lane;
                float s = (j < NT) ? srow[j] + brow[j] : -1e30f;
                v[tt] = s;
                mx = fmaxf(mx, s);
            }
            #pragma unroll
            for (int o = 16; o; o >>= 1)
                mx = fmaxf(mx, __shfl_xor_sync(0xffffffffu, mx, o));
            float sum = 0.f;
            #pragma unroll
            for (int tt = 0; tt < 11; tt++) {
                int j = tt * 32 + lane;
                if (j < NT) { float e = __expf(v[tt] - mx); v[tt] = e; sum += e; }
                else v[tt] = 0.f;
            }
            #pragma unroll
            for (int o = 16; o; o >>= 1)
                sum += __shfl_xor_sync(0xffffffffu, sum, o);
            float inv = __frcp_rn(sum);
            #pragma unroll
            for (int tt = 0; tt < 11; tt++) {
                int j = tt * 32 + lane;
                srow[j] = v[tt] * inv;      // pads (343..351) get 0
            }
        }
        __syncthreads();

        // ---- O = P @ V : warp -> (row-tile warp&3, col-tile warp>>2) ----
        {
            int rt = warp & 3, ct = warp >> 2;
            wmma::fragment<wmma::accumulator, 16, 16, 8, float> acc0, acc1;
            wmma::fill_fragment(acc0, 0.0f);
            wmma::fill_fragment(acc1, 0.0f);
            #pragma unroll 4
            for (int kk = 0; kk < NTP / 8; kk += 2) {
                wmma::fragment<wmma::matrix_a, 16, 16, 8, wmma::precision::tf32,
                               wmma::row_major> pa, pb;
                wmma::fragment<wmma::matrix_b, 16, 16, 8, wmma::precision::tf32,
                               wmma::row_major> va, vb;
                wmma::load_matrix_sync(pa, &ss[rt * 16 * SST + kk * 8], SST);
                wmma::load_matrix_sync(va, &vs[kk * 8 * KS2 + ct * 16], KS2);
                CVT_FRAG(pa); CVT_FRAG(va);
                wmma::mma_sync(acc0, pa, va, acc0);
                wmma::load_matrix_sync(pb, &ss[rt * 16 * SST + (kk + 1) * 8], SST);
                wmma::load_matrix_sync(vb, &vs[(kk + 1) * 8 * KS2 + ct * 16], KS2);
                CVT_FRAG(pb); CVT_FRAG(vb);
                wmma::mma_sync(acc1, pb, vb, acc1);
            }
            #pragma unroll
            for (int e = 0; e < acc0.num_elements; e++)
                acc0.x[e] += acc1.x[e];
            wmma::store_matrix_sync(&os[warp * 320], acc0, 20, wmma::mem_row_major);
            __syncwarp();
            #pragma unroll
            for (int e = 0; e < 8; e++) {
                int idx = lane * 8 + e;
                int row = idx >> 4, col = idx & 15;
                int r = qb + rt * 16 + row;
                if (r < NT)
                    g_ao[((size_t)b * NT + r) * CDIM + h * HD + ct * 16 + col] =
                        os[warp * 320 + row * 20 + col];
            }
        }
        __syncthreads();
    }
}

// ---------------- launch ----------------------------------------------------
extern "C" void kernel_launch(void* const* d_in, const int* in_sizes, int n_in,
                              void* d_out, int out_size) {
    const float* x      = (const float*)d_in[0];
    const float* w_qkv  = (const float*)d_in[1];
    const float* b_qkv  = (const float*)d_in[2];
    const float* w_proj = (const float*)d_in[3];
    const float* b_proj = (const float*)d_in[4];
    const float* table  = (const float*)d_in[5];
    const int*   ridx   = (const int*)d_in[6];
    float* out = (float*)d_out;

    bias_kernel<<<(NT*NT + 255) / 256, 256>>>(table, ridx);

    gemm_kernel<0><<<dim3(576 / BN, MROWS / BM), 256>>>(x, w_qkv, b_qkv, nullptr);

    const int smem_bytes = AT_SMEM_FLOATS * (int)sizeof(float);  // ~207 KB
    cudaFuncSetAttribute(attn_tc_kernel,
                         cudaFuncAttributeMaxDynamicSharedMemorySize, smem_bytes);
    attn_tc_kernel<<<B_ * NH, 256, smem_bytes>>>();

    gemm_kernel<1><<<dim3(CDIM / BN, MROWS / BM), 256>>>(nullptr, w_proj, b_proj, out);
}